// round 14
// baseline (speedup 1.0000x reference)
#include <cuda_runtime.h>
#include <math.h>

#define B_SZ   2048
#define INV_TEMP (1.0f/0.07f)
#define MARGIN_C 0.15f
// act tiles (16KB) + 8 warps * 5 * 2KB chunk ring (80KB)
#define DYN_SMEM (16384 + 8*5*2048)

#define FMA2(d,a,b,c) asm("fma.rn.f32x2 %0, %1, %2, %3;" : "=l"(d) : "l"(a), "l"(b), "l"(c))
#define UNPACK2(lo,hi,v) asm("mov.b64 {%0, %1}, %2;" : "=f"(lo), "=f"(hi) : "l"(v))

__device__ float        g_partial[B_SZ];
__device__ unsigned int g_count = 0;
__device__ float        g_dist[64][64];

typedef unsigned long long ull;

// ---- tiny precompute: dist[i][j] = ||pos_i - pos_j|| with zero diagonal ----
__global__ void dist_kernel(const float* __restrict__ cpos)
{
    __shared__ float s_pos[192];
    const int tid = threadIdx.x;          // 256 threads
    if (tid < 192) s_pos[tid] = cpos[tid];
    __syncthreads();
    #pragma unroll
    for (int e = 0; e < 16; ++e) {
        const int idx = tid * 16 + e;
        const int i = idx >> 6, j = idx & 63;
        float dx = s_pos[i*3]   - s_pos[j*3];
        float dy = s_pos[i*3+1] - s_pos[j*3+1];
        float dz = s_pos[i*3+2] - s_pos[j*3+2];
        float d2 = fmaf(dx,dx, fmaf(dy,dy, dz*dz));
        g_dist[i][j] = (i == j) ? 0.0f : sqrtf(d2);
    }
}

// issue one 2KB half-row chunk as a cp.async group (64B per lane, 4x16B)
__device__ __forceinline__ void issue_chunk(unsigned sdst, const float* gsrc, int lane)
{
    #pragma unroll
    for (int c = 0; c < 4; ++c) {
        asm volatile("cp.async.cg.shared.global [%0], [%1], 16;"
                     :: "r"(sdst + c*512 + lane*16), "l"(gsrc + c*128 + lane*4) : "memory");
    }
    asm volatile("cp.async.commit_group;" ::: "memory");
}

// chunk c (0..15, per warp): pass p=c>>2, sub=c&3 -> row 2p+(sub&1), half sub>>1
__device__ __forceinline__ int chunk_src_off(int c)
{
    const int row = ((c >> 2) << 1) + (c & 1);
    const int h   = (c >> 1) & 1;
    return row * 1024 + h * 512;
}

__global__ __launch_bounds__(256, 2)
void loss_kernel(const float* __restrict__ pred,
                 const int*   __restrict__ labels,
                 const float* __restrict__ emb,
                 const float* __restrict__ conn,
                 float* __restrict__ out)
{
    extern __shared__ __align__(16) float dyn[];
    float* s_act_emb  = dyn;              // [4][1024], 16 KB
    float* s_stream   = dyn + 4096;       // [8 warps][5][512 floats], 80 KB

    __shared__ float s_pred[64];
    __shared__ int   s_lab[64];
    __shared__ int   s_act[4];
    __shared__ int   s_inact[60];
    __shared__ float s_topk;
    __shared__ float s_part[64][5][4];    // 4-lane partials: [row][d0..d3,n][lane]
    __shared__ float s_dot[4][64];
    __shared__ float s_rn[64];
    __shared__ float s_bce[64], s_pl[64], s_sp[64], s_nw[64];
    __shared__ int   s_islast;
    __shared__ float s_red[256];

    const int b   = blockIdx.x;
    const int tid = threadIdx.x;
    const int w   = tid >> 5, lane = tid & 31;

    // ---------------- Phase A (no sync): smem scalars + per-warp act list ----------------
    if (tid < 64) { s_pred[tid] = pred[b*64 + tid]; s_lab[tid] = labels[b*64 + tid]; }

    const int lab0 = labels[b*64 + lane];
    const int lab1 = labels[b*64 + 32 + lane];
    const unsigned m0 = __ballot_sync(0xffffffffu, lab0 != 0);
    const unsigned m1 = __ballot_sync(0xffffffffu, lab1 != 0);
    int act0, act1, act2, act3;
    {
        int a[4]; int na = 0;
        unsigned mm = m0;
        while (mm) { a[na++] = __ffs(mm) - 1; mm &= mm - 1; }
        mm = m1;
        while (mm) { a[na++] = 32 + __ffs(mm) - 1; mm &= mm - 1; }
        act0 = a[0]; act1 = a[1]; act2 = a[2]; act3 = a[3];
    }

    if (w == 0) {
        const unsigned below = (1u << lane) - 1u;
        if (lab0) s_act[__popc(m0 & below)] = lane;
        if (lab1) s_act[__popc(m0) + __popc(m1 & below)] = 32 + lane;
        const unsigned i0 = ~m0, i1 = ~m1;
        if (!lab0) s_inact[__popc(i0 & below)] = lane;
        if (!lab1) s_inact[__popc(i0) + __popc(i1 & below)] = 32 + lane;
    }

    // ---------------- Phase B: stage 4 active rows (plain LDG->STS) ----------------
    {
        const float4* base = (const float4*)(emb + (size_t)b * 65536);
        ((float4*)s_act_emb)[tid]       = base[(size_t)act0 * 256 + tid];
        ((float4*)s_act_emb)[tid + 256] = base[(size_t)act1 * 256 + tid];
        ((float4*)s_act_emb)[tid + 512] = base[(size_t)act2 * 256 + tid];
        ((float4*)s_act_emb)[tid + 768] = base[(size_t)act3 * 256 + tid];
    }

    // stream pipeline prologue: chunks 0..4 of this warp's 8 rows in flight (3-deep lead)
    const float* rowbase = emb + (size_t)b * 65536 + (size_t)(w * 8) * 1024;
    unsigned sbuf0;
    {
        unsigned sbase;
        asm("{ .reg .u64 t; cvta.to.shared.u64 t, %1; cvt.u32.u64 %0, t; }"
            : "=r"(sbase) : "l"(s_stream));
        sbuf0 = sbase + (unsigned)(w * 10240);
    }
    issue_chunk(sbuf0 + 0*2048, rowbase + chunk_src_off(0), lane);
    issue_chunk(sbuf0 + 1*2048, rowbase + chunk_src_off(1), lane);
    issue_chunk(sbuf0 + 2*2048, rowbase + chunk_src_off(2), lane);
    issue_chunk(sbuf0 + 3*2048, rowbase + chunk_src_off(3), lane);
    issue_chunk(sbuf0 + 4*2048, rowbase + chunk_src_off(4), lane);

    // warp 0: parallel top-4 + IoU while loads are in flight
    if (w == 0) {
        float w0 = pred[b*64 + lane];
        float w1 = pred[b*64 + 32 + lane];
        int inter = 0;
        #pragma unroll
        for (int r = 0; r < 4; ++r) {
            float bv; int bi;
            if (w1 > w0) { bv = w1; bi = lane + 32; } else { bv = w0; bi = lane; }
            #pragma unroll
            for (int off = 16; off; off >>= 1) {
                float ov = __shfl_xor_sync(0xffffffffu, bv, off);
                int   oi = __shfl_xor_sync(0xffffffffu, bi, off);
                if (ov > bv || (ov == bv && oi < bi)) { bv = ov; bi = oi; }
            }
            inter += (bi < 32) ? (int)((m0 >> bi) & 1u) : (int)((m1 >> (bi - 32)) & 1u);
            if (bi == lane)      w0 = -1e30f;
            if (bi == lane + 32) w1 = -1e30f;
        }
        if (lane == 0) {
            float un = (float)(8 - inter);
            s_topk = 1.0f - (float)inter / (un + 1e-8f);
        }
    }
    __syncthreads();   // act tiles visible to all warps

    // ---- Phase C: 4 passes x 2 rows, 2 half-passes each, 5-chunk cp.async ring ----
    {
        const ull zero = 0ull;
        const ulonglong2* acts = (const ulonglong2*)s_act_emb;   // 4 rows x 256 ull2
        #pragma unroll
        for (int p = 0; p < 4; ++p) {
            ull d00=zero,d01=zero,d02=zero,d03=zero,n0=zero;
            ull d10=zero,d11=zero,d12=zero,d13=zero,n1=zero;
            #pragma unroll
            for (int h = 0; h < 2; ++h) {
                const int q = 2*p + h;                 // halfpass 0..7
                if      (q == 7) { asm volatile("cp.async.wait_group 0;" ::: "memory"); }
                else if (q == 6) { asm volatile("cp.async.wait_group 2;" ::: "memory"); }
                else             { asm volatile("cp.async.wait_group 3;" ::: "memory"); }

                const int c0 = 4*p + 2*h, c1 = c0 + 1; // chunks: rows 2p,2p+1 half h
                const ulonglong2* cur0 =
                    (const ulonglong2*)(s_stream + (size_t)w * 2560 + (size_t)(c0 % 5) * 512);
                const ulonglong2* cur1 =
                    (const ulonglong2*)(s_stream + (size_t)w * 2560 + (size_t)(c1 % 5) * 512);
                const int abase = h * 128;

                #pragma unroll
                for (int ii = 0; ii < 4; ++ii) {
                    const int i = lane + ii * 32;      // 0..127 within half-row
                    ulonglong2 e0 = cur0[i], e1 = cur1[i];
                    ulonglong2 a0 = acts[abase + i];
                    FMA2(d00,e0.x,a0.x,d00); FMA2(d00,e0.y,a0.y,d00);
                    FMA2(d10,e1.x,a0.x,d10); FMA2(d10,e1.y,a0.y,d10);
                    ulonglong2 a1 = acts[abase + i + 256];
                    FMA2(d01,e0.x,a1.x,d01); FMA2(d01,e0.y,a1.y,d01);
                    FMA2(d11,e1.x,a1.x,d11); FMA2(d11,e1.y,a1.y,d11);
                    ulonglong2 a2 = acts[abase + i + 512];
                    FMA2(d02,e0.x,a2.x,d02); FMA2(d02,e0.y,a2.y,d02);
                    FMA2(d12,e1.x,a2.x,d12); FMA2(d12,e1.y,a2.y,d12);
                    ulonglong2 a3 = acts[abase + i + 768];
                    FMA2(d03,e0.x,a3.x,d03); FMA2(d03,e0.y,a3.y,d03);
                    FMA2(d13,e1.x,a3.x,d13); FMA2(d13,e1.y,a3.y,d13);
                    FMA2(n0 ,e0.x,e0.x,n0 ); FMA2(n0 ,e0.y,e0.y,n0 );
                    FMA2(n1 ,e1.x,e1.x,n1 ); FMA2(n1 ,e1.y,e1.y,n1 );
                }

                // refill the two buffers just freed (chunks 2q+5 -> buf 2q%5, 2q+6 -> (2q+1)%5)
                {
                    const int c4 = 2*q + 5, c5 = 2*q + 6;
                    if (c4 < 16)
                        issue_chunk(sbuf0 + (unsigned)((c4 % 5) * 2048),
                                    rowbase + chunk_src_off(c4), lane);
                    if (c5 < 16)
                        issue_chunk(sbuf0 + (unsigned)((c5 % 5) * 2048),
                                    rowbase + chunk_src_off(c5), lane);
                }
            }

            float v0,v1,v2,v3,v4,v5,v6,v7,v8,v9;
            { float lo,hi; UNPACK2(lo,hi,d00); v0=lo+hi; }
            { float lo,hi; UNPACK2(lo,hi,d01); v1=lo+hi; }
            { float lo,hi; UNPACK2(lo,hi,d02); v2=lo+hi; }
            { float lo,hi; UNPACK2(lo,hi,d03); v3=lo+hi; }
            { float lo,hi; UNPACK2(lo,hi,n0 ); v4=lo+hi; }
            { float lo,hi; UNPACK2(lo,hi,d10); v5=lo+hi; }
            { float lo,hi; UNPACK2(lo,hi,d11); v6=lo+hi; }
            { float lo,hi; UNPACK2(lo,hi,d12); v7=lo+hi; }
            { float lo,hi; UNPACK2(lo,hi,d13); v8=lo+hi; }
            { float lo,hi; UNPACK2(lo,hi,n1 ); v9=lo+hi; }
            // 3-level tree: lanes 0..3 hold a disjoint 4-way cover of the warp sum
            #pragma unroll
            for (int off = 16; off >= 4; off >>= 1) {
                v0 += __shfl_down_sync(0xffffffffu, v0, off);
                v1 += __shfl_down_sync(0xffffffffu, v1, off);
                v2 += __shfl_down_sync(0xffffffffu, v2, off);
                v3 += __shfl_down_sync(0xffffffffu, v3, off);
                v4 += __shfl_down_sync(0xffffffffu, v4, off);
                v5 += __shfl_down_sync(0xffffffffu, v5, off);
                v6 += __shfl_down_sync(0xffffffffu, v6, off);
                v7 += __shfl_down_sync(0xffffffffu, v7, off);
                v8 += __shfl_down_sync(0xffffffffu, v8, off);
                v9 += __shfl_down_sync(0xffffffffu, v9, off);
            }
            if (lane < 4) {
                const int j0 = w * 8 + 2*p;
                s_part[j0][0][lane]   = v0; s_part[j0][1][lane]   = v1;
                s_part[j0][2][lane]   = v2; s_part[j0][3][lane]   = v3;
                s_part[j0][4][lane]   = v4;
                s_part[j0+1][0][lane] = v5; s_part[j0+1][1][lane] = v6;
                s_part[j0+1][2][lane] = v7; s_part[j0+1][3][lane] = v8;
                s_part[j0+1][4][lane] = v9;
            }
        }
    }
    __syncthreads();

    // ---------------- Phase D (warp-parallel) ----------------
    // combine 4-lane partials: 256 threads cover the whole 4x64 dot matrix
    {
        const int c = tid & 63, k = tid >> 6;
        s_dot[k][c] = (s_part[c][k][0] + s_part[c][k][1])
                    + (s_part[c][k][2] + s_part[c][k][3]);
    }
    if (tid < 64) {
        float nv = (s_part[tid][4][0] + s_part[tid][4][1])
                 + (s_part[tid][4][2] + s_part[tid][4][3]);
        s_rn[tid] = 1.0f / fmaxf(sqrtf(nv), 1e-12f);
        const float p   = s_pred[tid];
        const int   lab = s_lab[tid];
        s_bce[tid] = lab ? logf(p) : log1pf(-p);
        s_pl[tid]  = lab ? p : 0.0f;
    }

    // network + spatial: each warp does 8 rows of conn / Dist (L2-resident)
    {
        const float pl0 = s_pred[lane],        pl1 = s_pred[lane + 32];
        const float ml0 = (pl0 > 0.5f) ? 1.0f : 0.0f;
        const float ml1 = (pl1 > 0.5f) ? 1.0f : 0.0f;
        #pragma unroll
        for (int rr = 0; rr < 8; ++rr) {
            const int r = w * 8 + rr;
            float t1 = fmaf(conn[r*64 + lane],   pl0, conn[r*64 + 32 + lane]   * pl1);
            float t2 = fmaf(g_dist[r][lane],     ml0, g_dist[r][lane + 32]     * ml1);
            #pragma unroll
            for (int off = 16; off; off >>= 1) {
                t1 += __shfl_down_sync(0xffffffffu, t1, off);
                t2 += __shfl_down_sync(0xffffffffu, t2, off);
            }
            if (lane == 0) {
                s_nw[r] = t1 * s_pred[r];
                s_sp[r] = t2 * ((s_pred[r] > 0.5f) ? 1.0f : 0.0f);
            }
        }
    }
    __syncthreads();

    // contrastive: 12 pairs in warp 0
    float ce = 0.0f;
    if (tid < 12) {
        const int p  = tid;
        const int k  = p / 3;
        const int jo = p % 3;
        const int col = jo + (jo >= k ? 1 : 0);
        const int ck = s_act[k];
        const int cj = s_act[col];
        const float rk = s_rn[ck];
        const float l0 = s_dot[k][cj] * rk * s_rn[cj] * INV_TEMP;
        const int base = 20 * jo;
        float mx = l0;
        #pragma unroll
        for (int n = 0; n < 20; ++n) {
            int c = s_inact[base + n];
            float vv = s_dot[k][c] * rk * s_rn[c] * INV_TEMP;
            mx = fmaxf(mx, vv);
        }
        float ssum = expf(l0 - mx);
        #pragma unroll
        for (int n = 0; n < 20; ++n) {
            int c = s_inact[base + n];
            float vv = s_dot[k][c] * rk * s_rn[c] * INV_TEMP;
            ssum += expf(vv - mx);
        }
        ce = logf(ssum) + mx - l0;
    }
    if (tid < 32) {
        #pragma unroll
        for (int off = 16; off; off >>= 1) ce += __shfl_down_sync(0xffffffffu, ce, off);
    }

    if (tid < 32) {
        float r_bce = s_bce[tid] + s_bce[tid+32];
        float r_pl  = s_pl [tid] + s_pl [tid+32];
        float r_p   = s_pred[tid] + s_pred[tid+32];
        float r_lab = (float)s_lab[tid] + (float)s_lab[tid+32];
        float r_sp  = s_sp[tid] + s_sp[tid+32];
        float r_nw  = s_nw[tid] + s_nw[tid+32];
        float pm0 = (s_pred[tid] > 0.5f) ? 1.0f : 0.0f;
        float pm1 = (s_pred[tid+32] > 0.5f) ? 1.0f : 0.0f;
        float r_m = pm0 + pm1;
        #pragma unroll
        for (int off = 16; off; off >>= 1) {
            r_bce += __shfl_down_sync(0xffffffffu, r_bce, off);
            r_pl  += __shfl_down_sync(0xffffffffu, r_pl , off);
            r_p   += __shfl_down_sync(0xffffffffu, r_p  , off);
            r_lab += __shfl_down_sync(0xffffffffu, r_lab, off);
            r_sp  += __shfl_down_sync(0xffffffffu, r_sp , off);
            r_nw  += __shfl_down_sync(0xffffffffu, r_nw , off);
            r_m   += __shfl_down_sync(0xffffffffu, r_m  , off);
        }
        if (tid == 0) {
            float score_b    = -r_bce * (1.0f/64.0f);
            float act_mean   = r_pl / r_lab;
            float inact_mean = (r_p - r_pl) / (64.0f - r_lab);
            float margin_b   = fmaxf(MARGIN_C - (act_mean - inact_mean), 0.0f);
            float contr_b    = ce * (1.0f/12.0f);
            float nm         = r_m;
            float spatial_b  = (nm >= 2.0f) ? r_sp / fmaxf(nm*(nm-1.0f), 1.0f) : 0.0f;
            float net_b      = -r_nw * (1.0f/4096.0f);
            g_partial[b] = 3.0f*score_b + 1.0f*margin_b + 2.0f*s_topk
                         + 1.0f*contr_b + 0.5f*spatial_b + 0.5f*net_b;
        }
    }

    // ---------------- fused final reduction (last block) ----------------
    if (tid == 0) {
        __threadfence();
        unsigned int v = atomicAdd(&g_count, 1u);
        s_islast = (v == (unsigned)(B_SZ - 1));
    }
    __syncthreads();
    if (s_islast) {
        float s = 0.0f;
        for (int i = tid; i < B_SZ; i += 256) s += g_partial[i];
        s_red[tid] = s;
        __syncthreads();
        for (int o = 128; o > 0; o >>= 1) {
            if (tid < o) s_red[tid] += s_red[tid + o];
            __syncthreads();
        }
        if (tid == 0) { out[0] = s_red[0] * (1.0f / (float)B_SZ); g_count = 0; }
    }
}

extern "C" void kernel_launch(void* const* d_in, const int* in_sizes, int n_in,
                              void* d_out, int out_size)
{
    const float* pred = (const float*)d_in[0];
    const int*   lab  = (const int*)  d_in[1];
    const float* emb  = (const float*)d_in[2];
    const float* cpos = (const float*)d_in[3];
    const float* conn = (const float*)d_in[4];
    static int attr_done = 0;
    if (!attr_done) {
        cudaFuncSetAttribute(loss_kernel,
                             cudaFuncAttributeMaxDynamicSharedMemorySize, DYN_SMEM);
        attr_done = 1;
    }
    dist_kernel<<<1, 256>>>(cpos);
    loss_kernel<<<B_SZ, 256, DYN_SMEM>>>(pred, lab, emb, conn, (float*)d_out);
}

// round 16
// speedup vs baseline: 1.0078x; 1.0078x over previous
#include <cuda_runtime.h>
#include <math.h>

#define B_SZ   2048
#define INV_TEMP (1.0f/0.07f)
#define MARGIN_C 0.15f
// act tiles (16KB) + 8 warps * 5 * 2KB chunk ring (80KB)
#define DYN_SMEM (16384 + 8*5*2048)

#define FMA2(d,a,b,c) asm("fma.rn.f32x2 %0, %1, %2, %3;" : "=l"(d) : "l"(a), "l"(b), "l"(c))
#define UNPACK2(lo,hi,v) asm("mov.b64 {%0, %1}, %2;" : "=f"(lo), "=f"(hi) : "l"(v))

__device__ float        g_partial[B_SZ];
__device__ unsigned int g_count = 0;
__device__ float        g_dist[64][64];

typedef unsigned long long ull;

// ---- tiny precompute: dist[i][j] = ||pos_i - pos_j|| with zero diagonal ----
__global__ void dist_kernel(const float* __restrict__ cpos)
{
    __shared__ float s_pos[192];
    const int tid = threadIdx.x;          // 256 threads
    if (tid < 192) s_pos[tid] = cpos[tid];
    __syncthreads();
    #pragma unroll
    for (int e = 0; e < 16; ++e) {
        const int idx = tid * 16 + e;
        const int i = idx >> 6, j = idx & 63;
        float dx = s_pos[i*3]   - s_pos[j*3];
        float dy = s_pos[i*3+1] - s_pos[j*3+1];
        float dz = s_pos[i*3+2] - s_pos[j*3+2];
        float d2 = fmaf(dx,dx, fmaf(dy,dy, dz*dz));
        g_dist[i][j] = (i == j) ? 0.0f : sqrtf(d2);
    }
}

// issue one 2KB half-row chunk as a cp.async group (64B per lane, 4x16B)
__device__ __forceinline__ void issue_chunk(unsigned sdst, const float* gsrc, int lane)
{
    #pragma unroll
    for (int c = 0; c < 4; ++c) {
        asm volatile("cp.async.cg.shared.global [%0], [%1], 16;"
                     :: "r"(sdst + c*512 + lane*16), "l"(gsrc + c*128 + lane*4) : "memory");
    }
    asm volatile("cp.async.commit_group;" ::: "memory");
}

// chunk c (0..15, per warp): pass P=c>>3, s=c&7 -> half s>>2, row 4P+(s&3)
__device__ __forceinline__ int chunk_src_off(int c)
{
    const int row = ((c >> 3) << 2) + (c & 3);
    const int h   = (c >> 2) & 1;
    return row * 1024 + h * 512;
}

__global__ __launch_bounds__(256, 2)
void loss_kernel(const float* __restrict__ pred,
                 const int*   __restrict__ labels,
                 const float* __restrict__ emb,
                 const float* __restrict__ conn,
                 float* __restrict__ out)
{
    extern __shared__ __align__(16) float dyn[];
    float* s_act_emb  = dyn;              // [4][1024], 16 KB
    float* s_stream   = dyn + 4096;       // [8 warps][5][512 floats], 80 KB

    __shared__ float s_pred[64];
    __shared__ int   s_lab[64];
    __shared__ int   s_act[4];
    __shared__ int   s_inact[60];
    __shared__ float s_topk;
    __shared__ float s_part[64][5][4];    // 4-lane partials: [row][d0..d3,n][lane]
    __shared__ float s_dot[4][64];
    __shared__ float s_rn[64];
    __shared__ float s_bce[64], s_pl[64], s_sp[64], s_nw[64];
    __shared__ int   s_islast;
    __shared__ float s_red[256];

    const int b   = blockIdx.x;
    const int tid = threadIdx.x;
    const int w   = tid >> 5, lane = tid & 31;

    // ---------------- Phase A (no sync): smem scalars + per-warp act list ----------------
    if (tid < 64) { s_pred[tid] = pred[b*64 + tid]; s_lab[tid] = labels[b*64 + tid]; }

    const int lab0 = labels[b*64 + lane];
    const int lab1 = labels[b*64 + 32 + lane];
    const unsigned m0 = __ballot_sync(0xffffffffu, lab0 != 0);
    const unsigned m1 = __ballot_sync(0xffffffffu, lab1 != 0);
    int act0, act1, act2, act3;
    {
        int a[4]; int na = 0;
        unsigned mm = m0;
        while (mm) { a[na++] = __ffs(mm) - 1; mm &= mm - 1; }
        mm = m1;
        while (mm) { a[na++] = 32 + __ffs(mm) - 1; mm &= mm - 1; }
        act0 = a[0]; act1 = a[1]; act2 = a[2]; act3 = a[3];
    }

    if (w == 0) {
        const unsigned below = (1u << lane) - 1u;
        if (lab0) s_act[__popc(m0 & below)] = lane;
        if (lab1) s_act[__popc(m0) + __popc(m1 & below)] = 32 + lane;
        const unsigned i0 = ~m0, i1 = ~m1;
        if (!lab0) s_inact[__popc(i0 & below)] = lane;
        if (!lab1) s_inact[__popc(i0) + __popc(i1 & below)] = 32 + lane;
    }

    // ---------------- Phase B: stage 4 active rows (plain LDG->STS) ----------------
    {
        const float4* base = (const float4*)(emb + (size_t)b * 65536);
        ((float4*)s_act_emb)[tid]       = base[(size_t)act0 * 256 + tid];
        ((float4*)s_act_emb)[tid + 256] = base[(size_t)act1 * 256 + tid];
        ((float4*)s_act_emb)[tid + 512] = base[(size_t)act2 * 256 + tid];
        ((float4*)s_act_emb)[tid + 768] = base[(size_t)act3 * 256 + tid];
    }

    // stream pipeline prologue: chunks 0..4 of this warp's 8 rows in flight
    const float* rowbase = emb + (size_t)b * 65536 + (size_t)(w * 8) * 1024;
    unsigned sbuf0;
    {
        unsigned sbase;
        asm("{ .reg .u64 t; cvta.to.shared.u64 t, %1; cvt.u32.u64 %0, t; }"
            : "=r"(sbase) : "l"(s_stream));
        sbuf0 = sbase + (unsigned)(w * 10240);
    }
    issue_chunk(sbuf0 + 0*2048, rowbase + chunk_src_off(0), lane);
    issue_chunk(sbuf0 + 1*2048, rowbase + chunk_src_off(1), lane);
    issue_chunk(sbuf0 + 2*2048, rowbase + chunk_src_off(2), lane);
    issue_chunk(sbuf0 + 3*2048, rowbase + chunk_src_off(3), lane);
    issue_chunk(sbuf0 + 4*2048, rowbase + chunk_src_off(4), lane);

    // warp 0: parallel top-4 + IoU while loads are in flight
    if (w == 0) {
        float w0 = pred[b*64 + lane];
        float w1 = pred[b*64 + 32 + lane];
        int inter = 0;
        #pragma unroll
        for (int r = 0; r < 4; ++r) {
            float bv; int bi;
            if (w1 > w0) { bv = w1; bi = lane + 32; } else { bv = w0; bi = lane; }
            #pragma unroll
            for (int off = 16; off; off >>= 1) {
                float ov = __shfl_xor_sync(0xffffffffu, bv, off);
                int   oi = __shfl_xor_sync(0xffffffffu, bi, off);
                if (ov > bv || (ov == bv && oi < bi)) { bv = ov; bi = oi; }
            }
            inter += (bi < 32) ? (int)((m0 >> bi) & 1u) : (int)((m1 >> (bi - 32)) & 1u);
            if (bi == lane)      w0 = -1e30f;
            if (bi == lane + 32) w1 = -1e30f;
        }
        if (lane == 0) {
            float un = (float)(8 - inter);
            s_topk = 1.0f - (float)inter / (un + 1e-8f);
        }
    }
    __syncthreads();   // act tiles visible to all warps

    // ---- Phase C: 2 passes x 4 rows, 2 half-passes each, 5-chunk cp.async ring ----
    {
        const ull zero = 0ull;
        const ulonglong2* acts = (const ulonglong2*)s_act_emb;   // 4 rows x 256 ull2
        #pragma unroll
        for (int P = 0; P < 2; ++P) {
            // dRK: stream row R (of 4), act K; nR: norm of row R
            ull d00=zero,d01=zero,d02=zero,d03=zero,n0=zero;
            ull d10=zero,d11=zero,d12=zero,d13=zero,n1=zero;
            ull d20=zero,d21=zero,d22=zero,d23=zero,n2=zero;
            ull d30=zero,d31=zero,d32=zero,d33=zero,n3=zero;
            #pragma unroll
            for (int h = 0; h < 2; ++h) {
                const int q = 2*P + h;                 // halfpass 0..3
                if (q == 3) { asm volatile("cp.async.wait_group 0;" ::: "memory"); }
                else        { asm volatile("cp.async.wait_group 1;" ::: "memory"); }

                const int cb = 4*q;                    // chunks cb..cb+3 = rows 4P..4P+3, half h
                const ulonglong2* cur0 =
                    (const ulonglong2*)(s_stream + (size_t)w * 2560 + (size_t)((cb+0) % 5) * 512);
                const ulonglong2* cur1 =
                    (const ulonglong2*)(s_stream + (size_t)w * 2560 + (size_t)((cb+1) % 5) * 512);
                const ulonglong2* cur2 =
                    (const ulonglong2*)(s_stream + (size_t)w * 2560 + (size_t)((cb+2) % 5) * 512);
                const ulonglong2* cur3 =
                    (const ulonglong2*)(s_stream + (size_t)w * 2560 + (size_t)((cb+3) % 5) * 512);
                const int abase = h * 128;

                #pragma unroll
                for (int ii = 0; ii < 4; ++ii) {
                    const int i = lane + ii * 32;      // 0..127 within half-row
                    ulonglong2 e0 = cur0[i], e1 = cur1[i], e2 = cur2[i], e3 = cur3[i];
                    ulonglong2 a0 = acts[abase + i];
                    FMA2(d00,e0.x,a0.x,d00); FMA2(d00,e0.y,a0.y,d00);
                    FMA2(d10,e1.x,a0.x,d10); FMA2(d10,e1.y,a0.y,d10);
                    FMA2(d20,e2.x,a0.x,d20); FMA2(d20,e2.y,a0.y,d20);
                    FMA2(d30,e3.x,a0.x,d30); FMA2(d30,e3.y,a0.y,d30);
                    ulonglong2 a1 = acts[abase + i + 256];
                    FMA2(d01,e0.x,a1.x,d01); FMA2(d01,e0.y,a1.y,d01);
                    FMA2(d11,e1.x,a1.x,d11); FMA2(d11,e1.y,a1.y,d11);
                    FMA2(d21,e2.x,a1.x,d21); FMA2(d21,e2.y,a1.y,d21);
                    FMA2(d31,e3.x,a1.x,d31); FMA2(d31,e3.y,a1.y,d31);
                    ulonglong2 a2 = acts[abase + i + 512];
                    FMA2(d02,e0.x,a2.x,d02); FMA2(d02,e0.y,a2.y,d02);
                    FMA2(d12,e1.x,a2.x,d12); FMA2(d12,e1.y,a2.y,d12);
                    FMA2(d22,e2.x,a2.x,d22); FMA2(d22,e2.y,a2.y,d22);
                    FMA2(d32,e3.x,a2.x,d32); FMA2(d32,e3.y,a2.y,d32);
                    ulonglong2 a3 = acts[abase + i + 768];
                    FMA2(d03,e0.x,a3.x,d03); FMA2(d03,e0.y,a3.y,d03);
                    FMA2(d13,e1.x,a3.x,d13); FMA2(d13,e1.y,a3.y,d13);
                    FMA2(d23,e2.x,a3.x,d23); FMA2(d23,e2.y,a3.y,d23);
                    FMA2(d33,e3.x,a3.x,d33); FMA2(d33,e3.y,a3.y,d33);
                    FMA2(n0 ,e0.x,e0.x,n0 ); FMA2(n0 ,e0.y,e0.y,n0 );
                    FMA2(n1 ,e1.x,e1.x,n1 ); FMA2(n1 ,e1.y,e1.y,n1 );
                    FMA2(n2 ,e2.x,e2.x,n2 ); FMA2(n2 ,e2.y,e2.y,n2 );
                    FMA2(n3 ,e3.x,e3.x,n3 ); FMA2(n3 ,e3.y,e3.y,n3 );
                }

                // refill the 4 buffers just freed: chunks 4q+5..4q+8 -> bufs (4q..4q+3)%5
                #pragma unroll
                for (int j = 0; j < 4; ++j) {
                    const int c = 4*q + 5 + j;
                    if (c < 16)
                        issue_chunk(sbuf0 + (unsigned)((c % 5) * 2048),
                                    rowbase + chunk_src_off(c), lane);
                }
            }

            // epilogue: 20 values, 3-level tree -> lanes 0..3 hold 4-way partials
            float v0,v1,v2,v3,v4,v5,v6,v7,v8,v9,v10,v11,v12,v13,v14,v15,v16,v17,v18,v19;
            { float lo,hi; UNPACK2(lo,hi,d00); v0 =lo+hi; }
            { float lo,hi; UNPACK2(lo,hi,d01); v1 =lo+hi; }
            { float lo,hi; UNPACK2(lo,hi,d02); v2 =lo+hi; }
            { float lo,hi; UNPACK2(lo,hi,d03); v3 =lo+hi; }
            { float lo,hi; UNPACK2(lo,hi,n0 ); v4 =lo+hi; }
            { float lo,hi; UNPACK2(lo,hi,d10); v5 =lo+hi; }
            { float lo,hi; UNPACK2(lo,hi,d11); v6 =lo+hi; }
            { float lo,hi; UNPACK2(lo,hi,d12); v7 =lo+hi; }
            { float lo,hi; UNPACK2(lo,hi,d13); v8 =lo+hi; }
            { float lo,hi; UNPACK2(lo,hi,n1 ); v9 =lo+hi; }
            { float lo,hi; UNPACK2(lo,hi,d20); v10=lo+hi; }
            { float lo,hi; UNPACK2(lo,hi,d21); v11=lo+hi; }
            { float lo,hi; UNPACK2(lo,hi,d22); v12=lo+hi; }
            { float lo,hi; UNPACK2(lo,hi,d23); v13=lo+hi; }
            { float lo,hi; UNPACK2(lo,hi,n2 ); v14=lo+hi; }
            { float lo,hi; UNPACK2(lo,hi,d30); v15=lo+hi; }
            { float lo,hi; UNPACK2(lo,hi,d31); v16=lo+hi; }
            { float lo,hi; UNPACK2(lo,hi,d32); v17=lo+hi; }
            { float lo,hi; UNPACK2(lo,hi,d33); v18=lo+hi; }
            { float lo,hi; UNPACK2(lo,hi,n3 ); v19=lo+hi; }
            #pragma unroll
            for (int off = 16; off >= 4; off >>= 1) {
                v0 +=__shfl_down_sync(0xffffffffu,v0 ,off); v1 +=__shfl_down_sync(0xffffffffu,v1 ,off);
                v2 +=__shfl_down_sync(0xffffffffu,v2 ,off); v3 +=__shfl_down_sync(0xffffffffu,v3 ,off);
                v4 +=__shfl_down_sync(0xffffffffu,v4 ,off); v5 +=__shfl_down_sync(0xffffffffu,v5 ,off);
                v6 +=__shfl_down_sync(0xffffffffu,v6 ,off); v7 +=__shfl_down_sync(0xffffffffu,v7 ,off);
                v8 +=__shfl_down_sync(0xffffffffu,v8 ,off); v9 +=__shfl_down_sync(0xffffffffu,v9 ,off);
                v10+=__shfl_down_sync(0xffffffffu,v10,off); v11+=__shfl_down_sync(0xffffffffu,v11,off);
                v12+=__shfl_down_sync(0xffffffffu,v12,off); v13+=__shfl_down_sync(0xffffffffu,v13,off);
                v14+=__shfl_down_sync(0xffffffffu,v14,off); v15+=__shfl_down_sync(0xffffffffu,v15,off);
                v16+=__shfl_down_sync(0xffffffffu,v16,off); v17+=__shfl_down_sync(0xffffffffu,v17,off);
                v18+=__shfl_down_sync(0xffffffffu,v18,off); v19+=__shfl_down_sync(0xffffffffu,v19,off);
            }
            if (lane < 4) {
                const int j0 = w * 8 + 4*P;
                s_part[j0  ][0][lane] = v0;  s_part[j0  ][1][lane] = v1;
                s_part[j0  ][2][lane] = v2;  s_part[j0  ][3][lane] = v3;
                s_part[j0  ][4][lane] = v4;
                s_part[j0+1][0][lane] = v5;  s_part[j0+1][1][lane] = v6;
                s_part[j0+1][2][lane] = v7;  s_part[j0+1][3][lane] = v8;
                s_part[j0+1][4][lane] = v9;
                s_part[j0+2][0][lane] = v10; s_part[j0+2][1][lane] = v11;
                s_part[j0+2][2][lane] = v12; s_part[j0+2][3][lane] = v13;
                s_part[j0+2][4][lane] = v14;
                s_part[j0+3][0][lane] = v15; s_part[j0+3][1][lane] = v16;
                s_part[j0+3][2][lane] = v17; s_part[j0+3][3][lane] = v18;
                s_part[j0+3][4][lane] = v19;
            }
        }
    }
    __syncthreads();

    // ---------------- Phase D (warp-parallel) ----------------
    // combine 4-lane partials: 256 threads cover the whole 4x64 dot matrix
    {
        const int c = tid & 63, k = tid >> 6;
        s_dot[k][c] = (s_part[c][k][0] + s_part[c][k][1])
                    + (s_part[c][k][2] + s_part[c][k][3]);
    }
    if (tid < 64) {
        float nv = (s_part[tid][4][0] + s_part[tid][4][1])
                 + (s_part[tid][4][2] + s_part[tid][4][3]);
        s_rn[tid] = 1.0f / fmaxf(sqrtf(nv), 1e-12f);
        const float p   = s_pred[tid];
        const int   lab = s_lab[tid];
        s_bce[tid] = lab ? logf(p) : log1pf(-p);
        s_pl[tid]  = lab ? p : 0.0f;
    }

    // network + spatial: each warp does 8 rows of conn / Dist (L2-resident)
    {
        const float pl0 = s_pred[lane],        pl1 = s_pred[lane + 32];
        const float ml0 = (pl0 > 0.5f) ? 1.0f : 0.0f;
        const float ml1 = (pl1 > 0.5f) ? 1.0f : 0.0f;
        #pragma unroll
        for (int rr = 0; rr < 8; ++rr) {
            const int r = w * 8 + rr;
            float t1 = fmaf(conn[r*64 + lane],   pl0, conn[r*64 + 32 + lane]   * pl1);
            float t2 = fmaf(g_dist[r][lane],     ml0, g_dist[r][lane + 32]     * ml1);
            #pragma unroll
            for (int off = 16; off; off >>= 1) {
                t1 += __shfl_down_sync(0xffffffffu, t1, off);
                t2 += __shfl_down_sync(0xffffffffu, t2, off);
            }
            if (lane == 0) {
                s_nw[r] = t1 * s_pred[r];
                s_sp[r] = t2 * ((s_pred[r] > 0.5f) ? 1.0f : 0.0f);
            }
        }
    }
    __syncthreads();

    // contrastive: 12 pairs in warp 0
    float ce = 0.0f;
    if (tid < 12) {
        const int p  = tid;
        const int k  = p / 3;
        const int jo = p % 3;
        const int col = jo + (jo >= k ? 1 : 0);
        const int ck = s_act[k];
        const int cj = s_act[col];
        const float rk = s_rn[ck];
        const float l0 = s_dot[k][cj] * rk * s_rn[cj] * INV_TEMP;
        const int base = 20 * jo;
        float mx = l0;
        #pragma unroll
        for (int n = 0; n < 20; ++n) {
            int c = s_inact[base + n];
            float vv = s_dot[k][c] * rk * s_rn[c] * INV_TEMP;
            mx = fmaxf(mx, vv);
        }
        float ssum = expf(l0 - mx);
        #pragma unroll
        for (int n = 0; n < 20; ++n) {
            int c = s_inact[base + n];
            float vv = s_dot[k][c] * rk * s_rn[c] * INV_TEMP;
            ssum += expf(vv - mx);
        }
        ce = logf(ssum) + mx - l0;
    }
    if (tid < 32) {
        #pragma unroll
        for (int off = 16; off; off >>= 1) ce += __shfl_down_sync(0xffffffffu, ce, off);
    }

    if (tid < 32) {
        float r_bce = s_bce[tid] + s_bce[tid+32];
        float r_pl  = s_pl [tid] + s_pl [tid+32];
        float r_p   = s_pred[tid] + s_pred[tid+32];
        float r_lab = (float)s_lab[tid] + (float)s_lab[tid+32];
        float r_sp  = s_sp[tid] + s_sp[tid+32];
        float r_nw  = s_nw[tid] + s_nw[tid+32];
        float pm0 = (s_pred[tid] > 0.5f) ? 1.0f : 0.0f;
        float pm1 = (s_pred[tid+32] > 0.5f) ? 1.0f : 0.0f;
        float r_m = pm0 + pm1;
        #pragma unroll
        for (int off = 16; off; off >>= 1) {
            r_bce += __shfl_down_sync(0xffffffffu, r_bce, off);
            r_pl  += __shfl_down_sync(0xffffffffu, r_pl , off);
            r_p   += __shfl_down_sync(0xffffffffu, r_p  , off);
            r_lab += __shfl_down_sync(0xffffffffu, r_lab, off);
            r_sp  += __shfl_down_sync(0xffffffffu, r_sp , off);
            r_nw  += __shfl_down_sync(0xffffffffu, r_nw , off);
            r_m   += __shfl_down_sync(0xffffffffu, r_m  , off);
        }
        if (tid == 0) {
            float score_b    = -r_bce * (1.0f/64.0f);
            float act_mean   = r_pl / r_lab;
            float inact_mean = (r_p - r_pl) / (64.0f - r_lab);
            float margin_b   = fmaxf(MARGIN_C - (act_mean - inact_mean), 0.0f);
            float contr_b    = ce * (1.0f/12.0f);
            float nm         = r_m;
            float spatial_b  = (nm >= 2.0f) ? r_sp / fmaxf(nm*(nm-1.0f), 1.0f) : 0.0f;
            float net_b      = -r_nw * (1.0f/4096.0f);
            g_partial[b] = 3.0f*score_b + 1.0f*margin_b + 2.0f*s_topk
                         + 1.0f*contr_b + 0.5f*spatial_b + 0.5f*net_b;
        }
    }

    // ---------------- fused final reduction (last block) ----------------
    if (tid == 0) {
        __threadfence();
        unsigned int v = atomicAdd(&g_count, 1u);
        s_islast = (v == (unsigned)(B_SZ - 1));
    }
    __syncthreads();
    if (s_islast) {
        float s = 0.0f;
        for (int i = tid; i < B_SZ; i += 256) s += g_partial[i];
        s_red[tid] = s;
        __syncthreads();
        for (int o = 128; o > 0; o >>= 1) {
            if (tid < o) s_red[tid] += s_red[tid + o];
            __syncthreads();
        }
        if (tid == 0) { out[0] = s_red[0] * (1.0f / (float)B_SZ); g_count = 0; }
    }
}

extern "C" void kernel_launch(void* const* d_in, const int* in_sizes, int n_in,
                              void* d_out, int out_size)
{
    const float* pred = (const float*)d_in[0];
    const int*   lab  = (const int*)  d_in[1];
    const float* emb  = (const float*)d_in[2];
    const float* cpos = (const float*)d_in[3];
    const float* conn = (const float*)d_in[4];
    static int attr_done = 0;
    if (!attr_done) {
        cudaFuncSetAttribute(loss_kernel,
                             cudaFuncAttributeMaxDynamicSharedMemorySize, DYN_SMEM);
        attr_done = 1;
    }
    dist_kernel<<<1, 256>>>(cpos);
    loss_kernel<<<B_SZ, 256, DYN_SMEM>>>(pred, lab, emb, conn, (float*)d_out);
}